// round 2
// baseline (speedup 1.0000x reference)
#include <cuda_runtime.h>
#include <cstdint>

#define N_NODES 100000
#define N_EDGES 1000000
#define DIM 64
#define BN_EPS 1e-5f

// ---------------- scratch (static device globals; no allocation allowed) ----
__device__ float g_sum[(size_t)N_NODES * DIM];   // aggregated messages (init = x for self loop)
__device__ float g_deg[N_NODES];                 // degree (init = 1 for self loop)
__device__ float g_out[(size_t)N_NODES * DIM];   // post-linear output
__device__ float g_bnsum[DIM];
__device__ float g_bnsq[DIM];
__device__ float g_scale[DIM];
__device__ float g_shift[DIM];

// ---------------- kernel 1: init accumulators ------------------------------
__global__ void k_init(const float4* __restrict__ x4) {
    int i = blockIdx.x * blockDim.x + threadIdx.x;   // over N_NODES*16 float4s
    if (i < N_NODES * (DIM / 4)) {
        reinterpret_cast<float4*>(g_sum)[i] = x4[i];
    }
    if (i < N_NODES) g_deg[i] = 1.0f;
    if (i < DIM) { g_bnsum[i] = 0.0f; g_bnsq[i] = 0.0f; }
}

// ---------------- kernel 2: edge gather + scatter-add ----------------------
// 16 lanes per edge, each lane moves one float4 (64 floats per edge).
// red.global.add.v4.f32: vectorized no-return reduction (sm_90+) -> 4x fewer
// L2 atomic ops than scalar atomicAdd.
// NOTE: edge_index is int32 (JAX demotes int64 -> int32 with x64 disabled).
__global__ void k_edges(const float4* __restrict__ x4,
                        const int* __restrict__ ei) {
    int t = blockIdx.x * blockDim.x + threadIdx.x;
    int e = t >> 4;
    if (e >= N_EDGES) return;
    int lane = t & 15;
    int src = ei[e];
    int dst = ei[N_EDGES + e];
    float4 v = x4[(size_t)src * (DIM / 4) + lane];
    float* p = g_sum + (size_t)dst * DIM + lane * 4;
    asm volatile("red.global.add.v4.f32 [%0], {%1, %2, %3, %4};"
                 :: "l"(p), "f"(v.x), "f"(v.y), "f"(v.z), "f"(v.w)
                 : "memory");
    if (lane == 0) atomicAdd(&g_deg[dst], 1.0f);
}

// ---------------- kernel 3: mean + linear + BN partial sums ----------------
// blockDim = (64, 4): 64 threads per node row (one per output channel),
// 4 node rows per block iteration. W is held transposed in smem so that
// Wt[k*64 + j] reads are conflict-free across lanes (consecutive j).
__global__ void k_linear(const float* __restrict__ w,
                         const float* __restrict__ b) {
    __shared__ float Wt[DIM * DIM];          // Wt[k][j] = w[j][k]
    __shared__ float s_aggr[4][DIM];
    __shared__ float s_red[2][4][DIM];

    int j = threadIdx.x;
    int y = threadIdx.y;
    int tid = y * DIM + j;

    for (int idx = tid; idx < DIM * DIM; idx += 256) {
        int jj = idx >> 6;
        int kk = idx & 63;
        Wt[kk * DIM + jj] = w[idx];
    }
    __syncthreads();

    float bj = b[j];
    float lsum = 0.0f, lsq = 0.0f;

    for (int base = blockIdx.x * 4; base < N_NODES; base += gridDim.x * 4) {
        int n = base + y;
        bool act = (n < N_NODES);
        if (act) {
            float d = g_deg[n];
            s_aggr[y][j] = g_sum[(size_t)n * DIM + j] / d;
        }
        __syncthreads();
        if (act) {
            float acc = bj;
            #pragma unroll
            for (int k = 0; k < DIM; k++)
                acc = fmaf(s_aggr[y][k], Wt[k * DIM + j], acc);
            g_out[(size_t)n * DIM + j] = acc;
            lsum += acc;
            lsq  += acc * acc;
        }
        __syncthreads();
    }

    s_red[0][y][j] = lsum;
    s_red[1][y][j] = lsq;
    __syncthreads();
    if (y == 0) {
        float s = s_red[0][0][j] + s_red[0][1][j] + s_red[0][2][j] + s_red[0][3][j];
        float q = s_red[1][0][j] + s_red[1][1][j] + s_red[1][2][j] + s_red[1][3][j];
        atomicAdd(&g_bnsum[j], s);
        atomicAdd(&g_bnsq[j], q);
    }
}

// ---------------- kernel 4: BN finalize (64 threads) -----------------------
__global__ void k_bnfin(const float* __restrict__ gamma,
                        const float* __restrict__ beta) {
    int j = threadIdx.x;
    float invN = 1.0f / (float)N_NODES;
    float mean = g_bnsum[j] * invN;
    float var  = g_bnsq[j] * invN - mean * mean;
    float inv  = rsqrtf(var + BN_EPS);
    float sc = gamma[j] * inv;
    g_scale[j] = sc;
    g_shift[j] = beta[j] - mean * sc;
}

// ---------------- kernel 5: scale/shift + residual + relu ------------------
__global__ void k_final(const float4* __restrict__ x4, float4* __restrict__ out4) {
    int i = blockIdx.x * blockDim.x + threadIdx.x;   // over N_NODES*16 float4s
    if (i >= N_NODES * (DIM / 4)) return;
    int c = (i & 15) * 4;   // channel base within row
    float4 o  = reinterpret_cast<const float4*>(g_out)[i];
    float4 xv = x4[i];
    float4 r;
    r.x = fmaxf(fmaf(o.x, g_scale[c + 0], g_shift[c + 0]) + xv.x, 0.0f);
    r.y = fmaxf(fmaf(o.y, g_scale[c + 1], g_shift[c + 1]) + xv.y, 0.0f);
    r.z = fmaxf(fmaf(o.z, g_scale[c + 2], g_shift[c + 2]) + xv.z, 0.0f);
    r.w = fmaxf(fmaf(o.w, g_scale[c + 3], g_shift[c + 3]) + xv.w, 0.0f);
    out4[i] = r;
}

// ---------------- launch ----------------------------------------------------
extern "C" void kernel_launch(void* const* d_in, const int* in_sizes, int n_in,
                              void* d_out, int out_size) {
    const float* x     = (const float*)d_in[0];       // [N, 64]
    const int*   ei    = (const int*)d_in[1];         // [2, E] int32 (JAX demotion)
    const float* w     = (const float*)d_in[2];       // [64, 64]
    const float* b     = (const float*)d_in[3];       // [64]
    const float* gamma = (const float*)d_in[4];       // [64]
    const float* beta  = (const float*)d_in[5];       // [64]
    float*       out   = (float*)d_out;               // [N, 64]

    const int vec = N_NODES * (DIM / 4);              // 1.6M float4s

    k_init<<<(vec + 255) / 256, 256>>>((const float4*)x);
    k_edges<<<(N_EDGES * 16 + 255) / 256, 256>>>((const float4*)x, ei);
    k_linear<<<1184, dim3(64, 4)>>>(w, b);
    k_bnfin<<<1, 64>>>(gamma, beta);
    k_final<<<(vec + 255) / 256, 256>>>((const float4*)x, (float4*)out);
}

// round 3
// speedup vs baseline: 1.0783x; 1.0783x over previous
#include <cuda_runtime.h>
#include <cstdint>

#define N_NODES 100000
#define N_EDGES 1000000
#define DIM 64
#define BN_EPS 1e-5f

#define SCAN_B 256
#define SCAN_NBLK ((N_NODES + SCAN_B - 1) / SCAN_B)   // 391

// ---------------- scratch (static device globals) ---------------------------
__device__ int   g_cnt[N_NODES];          // in-degree histogram
__device__ int   g_off[N_NODES + 1];      // CSR offsets (exclusive scan)
__device__ int   g_cursor[N_NODES];       // scatter cursors
__device__ int   g_perm[N_EDGES];         // src node per dst-sorted slot
__device__ int   g_blocksum[SCAN_NBLK];
__device__ int   g_blockoff[SCAN_NBLK];
__device__ float g_aggr[(size_t)N_NODES * DIM];   // mean-aggregated features
__device__ float g_out[(size_t)N_NODES * DIM];    // post-linear output
__device__ float g_bnsum[DIM];
__device__ float g_bnsq[DIM];
__device__ float g_scale[DIM];
__device__ float g_shift[DIM];

// ---------------- kernel 1: zero counters ----------------------------------
__global__ void k_zero() {
    int i = blockIdx.x * blockDim.x + threadIdx.x;
    if (i < N_NODES) g_cnt[i] = 0;
    if (i < DIM) { g_bnsum[i] = 0.0f; g_bnsq[i] = 0.0f; }
}

// ---------------- kernel 2: in-degree histogram -----------------------------
__global__ void k_hist(const int* __restrict__ ei) {
    int e = blockIdx.x * blockDim.x + threadIdx.x;
    if (e < N_EDGES) atomicAdd(&g_cnt[ei[N_EDGES + e]], 1);
}

// ---------------- kernels 3-5: exclusive scan of g_cnt ----------------------
__global__ void k_scan1() {                       // per-block reduce
    __shared__ int s[SCAN_B];
    int i = blockIdx.x * SCAN_B + threadIdx.x;
    s[threadIdx.x] = (i < N_NODES) ? g_cnt[i] : 0;
    __syncthreads();
    for (int st = SCAN_B / 2; st > 0; st >>= 1) {
        if (threadIdx.x < st) s[threadIdx.x] += s[threadIdx.x + st];
        __syncthreads();
    }
    if (threadIdx.x == 0) g_blocksum[blockIdx.x] = s[0];
}

__global__ void k_scan2() {                       // scan the 391 block sums
    __shared__ int s[512];
    int t = threadIdx.x;
    s[t] = (t < SCAN_NBLK) ? g_blocksum[t] : 0;
    __syncthreads();
    // Hillis-Steele inclusive
    for (int d = 1; d < 512; d <<= 1) {
        int v = (t >= d) ? s[t - d] : 0;
        __syncthreads();
        s[t] += v;
        __syncthreads();
    }
    if (t < SCAN_NBLK) g_blockoff[t] = (t == 0) ? 0 : s[t - 1];  // exclusive
    if (t == 0) g_off[N_NODES] = N_EDGES;
}

__global__ void k_scan3() {                       // local scan + block offset
    __shared__ int s[SCAN_B];
    int i = blockIdx.x * SCAN_B + threadIdx.x;
    int t = threadIdx.x;
    int v0 = (i < N_NODES) ? g_cnt[i] : 0;
    s[t] = v0;
    __syncthreads();
    for (int d = 1; d < SCAN_B; d <<= 1) {
        int v = (t >= d) ? s[t - d] : 0;
        __syncthreads();
        s[t] += v;
        __syncthreads();
    }
    if (i < N_NODES) {
        int excl = s[t] - v0 + g_blockoff[blockIdx.x];
        g_off[i] = excl;
        g_cursor[i] = excl;
    }
}

// ---------------- kernel 6: scatter src into dst-sorted order ---------------
__global__ void k_scatter(const int* __restrict__ ei) {
    int e = blockIdx.x * blockDim.x + threadIdx.x;
    if (e >= N_EDGES) return;
    int src = ei[e];
    int dst = ei[N_EDGES + e];
    int pos = atomicAdd(&g_cursor[dst], 1);
    g_perm[pos] = src;
}

// ---------------- kernel 7: dst-major aggregation (no atomics) --------------
// 16 lanes per node; lane carries one float4 (4 channels) in a register.
// Self-loop = init with x[n]; mean divide fused.
__global__ void k_aggr(const float4* __restrict__ x4) {
    int g    = blockIdx.x * (blockDim.x >> 4) + (threadIdx.x >> 4);
    int lane = threadIdx.x & 15;
    if (g >= N_NODES) return;
    int beg = g_off[g];
    int end = g_off[g + 1];
    float4 acc = x4[(size_t)g * (DIM / 4) + lane];    // self loop
    int i = beg;
    int s = (i < end) ? g_perm[i] : 0;
    while (i < end) {
        int sn = (i + 1 < end) ? g_perm[i + 1] : 0;   // prefetch next idx
        float4 v = x4[(size_t)s * (DIM / 4) + lane];
        acc.x += v.x; acc.y += v.y; acc.z += v.z; acc.w += v.w;
        s = sn;
        i++;
    }
    float inv = 1.0f / (float)(end - beg + 1);
    acc.x *= inv; acc.y *= inv; acc.z *= inv; acc.w *= inv;
    reinterpret_cast<float4*>(g_aggr)[(size_t)g * (DIM / 4) + lane] = acc;
}

// ---------------- kernel 8: linear + BN partial sums ------------------------
__global__ void k_linear(const float* __restrict__ w,
                         const float* __restrict__ b) {
    __shared__ float Wt[DIM * DIM];          // Wt[k][j] = w[j][k]
    __shared__ float s_aggr[4][DIM];
    __shared__ float s_red[2][4][DIM];

    int j = threadIdx.x;
    int y = threadIdx.y;
    int tid = y * DIM + j;

    for (int idx = tid; idx < DIM * DIM; idx += 256) {
        int jj = idx >> 6;
        int kk = idx & 63;
        Wt[kk * DIM + jj] = w[idx];
    }
    __syncthreads();

    float bj = b[j];
    float lsum = 0.0f, lsq = 0.0f;

    for (int base = blockIdx.x * 4; base < N_NODES; base += gridDim.x * 4) {
        int n = base + y;
        bool act = (n < N_NODES);
        if (act) s_aggr[y][j] = g_aggr[(size_t)n * DIM + j];
        __syncthreads();
        if (act) {
            float acc = bj;
            #pragma unroll
            for (int k = 0; k < DIM; k++)
                acc = fmaf(s_aggr[y][k], Wt[k * DIM + j], acc);
            g_out[(size_t)n * DIM + j] = acc;
            lsum += acc;
            lsq  += acc * acc;
        }
        __syncthreads();
    }

    s_red[0][y][j] = lsum;
    s_red[1][y][j] = lsq;
    __syncthreads();
    if (y == 0) {
        float s = s_red[0][0][j] + s_red[0][1][j] + s_red[0][2][j] + s_red[0][3][j];
        float q = s_red[1][0][j] + s_red[1][1][j] + s_red[1][2][j] + s_red[1][3][j];
        atomicAdd(&g_bnsum[j], s);
        atomicAdd(&g_bnsq[j], q);
    }
}

// ---------------- kernel 9: BN finalize (64 threads) ------------------------
__global__ void k_bnfin(const float* __restrict__ gamma,
                        const float* __restrict__ beta) {
    int j = threadIdx.x;
    float invN = 1.0f / (float)N_NODES;
    float mean = g_bnsum[j] * invN;
    float var  = g_bnsq[j] * invN - mean * mean;
    float inv  = rsqrtf(var + BN_EPS);
    float sc = gamma[j] * inv;
    g_scale[j] = sc;
    g_shift[j] = beta[j] - mean * sc;
}

// ---------------- kernel 10: scale/shift + residual + relu ------------------
__global__ void k_final(const float4* __restrict__ x4, float4* __restrict__ out4) {
    int i = blockIdx.x * blockDim.x + threadIdx.x;
    if (i >= N_NODES * (DIM / 4)) return;
    int c = (i & 15) * 4;
    float4 o  = reinterpret_cast<const float4*>(g_out)[i];
    float4 xv = x4[i];
    float4 r;
    r.x = fmaxf(fmaf(o.x, g_scale[c + 0], g_shift[c + 0]) + xv.x, 0.0f);
    r.y = fmaxf(fmaf(o.y, g_scale[c + 1], g_shift[c + 1]) + xv.y, 0.0f);
    r.z = fmaxf(fmaf(o.z, g_scale[c + 2], g_shift[c + 2]) + xv.z, 0.0f);
    r.w = fmaxf(fmaf(o.w, g_scale[c + 3], g_shift[c + 3]) + xv.w, 0.0f);
    out4[i] = r;
}

// ---------------- launch -----------------------------------------------------
extern "C" void kernel_launch(void* const* d_in, const int* in_sizes, int n_in,
                              void* d_out, int out_size) {
    const float* x     = (const float*)d_in[0];
    const int*   ei    = (const int*)d_in[1];
    const float* w     = (const float*)d_in[2];
    const float* b     = (const float*)d_in[3];
    const float* gamma = (const float*)d_in[4];
    const float* beta  = (const float*)d_in[5];
    float*       out   = (float*)d_out;

    const int vec = N_NODES * (DIM / 4);

    k_zero<<<SCAN_NBLK, SCAN_B>>>();
    k_hist<<<(N_EDGES + 255) / 256, 256>>>(ei);
    k_scan1<<<SCAN_NBLK, SCAN_B>>>();
    k_scan2<<<1, 512>>>();
    k_scan3<<<SCAN_NBLK, SCAN_B>>>();
    k_scatter<<<(N_EDGES + 255) / 256, 256>>>(ei);
    k_aggr<<<(N_NODES * 16 + 255) / 256, 256>>>((const float4*)x);
    k_linear<<<1184, dim3(64, 4)>>>(w, b);
    k_bnfin<<<1, 64>>>(gamma, beta);
    k_final<<<(vec + 255) / 256, 256>>>((const float4*)x, (float4*)out);
}

// round 5
// speedup vs baseline: 1.5269x; 1.4160x over previous
#include <cuda_runtime.h>
#include <cstdint>

#define N_NODES 100000
#define N_EDGES 1000000
#define DIM 64
#define BN_EPS 1e-5f

#define SCAN_B 256
#define SCAN_NBLK ((N_NODES + SCAN_B - 1) / SCAN_B)   // 391

#define GEMM_BM 128                                    // nodes per block
#define GEMM_NBLK ((N_NODES + GEMM_BM - 1) / GEMM_BM)  // 782

// ---------------- scratch (static device globals) ---------------------------
__device__ int   g_cnt[N_NODES];
__device__ int   g_off[N_NODES + 1];
__device__ int   g_cursor[N_NODES];
__device__ int   g_perm[N_EDGES];
__device__ int   g_blocksum[SCAN_NBLK];
__device__ int   g_blockoff[SCAN_NBLK];
__device__ float g_aggr[(size_t)N_NODES * DIM];
__device__ float g_out[(size_t)N_NODES * DIM];
__device__ float g_bnsum[DIM];
__device__ float g_bnsq[DIM];
__device__ float g_scale[DIM];
__device__ float g_shift[DIM];

// ---------------- kernel 1: zero counters ----------------------------------
__global__ void k_zero() {
    int i = blockIdx.x * blockDim.x + threadIdx.x;
    if (i < N_NODES) g_cnt[i] = 0;
    if (i < DIM) { g_bnsum[i] = 0.0f; g_bnsq[i] = 0.0f; }
}

// ---------------- kernel 2: in-degree histogram -----------------------------
__global__ void k_hist(const int* __restrict__ ei) {
    int e = blockIdx.x * blockDim.x + threadIdx.x;
    if (e < N_EDGES) atomicAdd(&g_cnt[ei[N_EDGES + e]], 1);
}

// ---------------- kernels 3-5: exclusive scan of g_cnt ----------------------
__global__ void k_scan1() {                       // per-block reduce (shuffle)
    __shared__ int wsum[SCAN_B / 32];
    int i = blockIdx.x * SCAN_B + threadIdx.x;
    int lane = threadIdx.x & 31, wid = threadIdx.x >> 5;
    int v = (i < N_NODES) ? g_cnt[i] : 0;
    #pragma unroll
    for (int d = 16; d > 0; d >>= 1) v += __shfl_down_sync(~0u, v, d);
    if (lane == 0) wsum[wid] = v;
    __syncthreads();
    if (threadIdx.x == 0) {
        int s = 0;
        #pragma unroll
        for (int k = 0; k < SCAN_B / 32; k++) s += wsum[k];
        g_blocksum[blockIdx.x] = s;
    }
}

__global__ void k_scan2() {                       // scan 391 block sums (512t)
    __shared__ int wsum[16];
    int t = threadIdx.x, lane = t & 31, wid = t >> 5;
    int own = (t < SCAN_NBLK) ? g_blocksum[t] : 0;
    int v = own;
    #pragma unroll
    for (int d = 1; d < 32; d <<= 1) {
        int n = __shfl_up_sync(~0u, v, d);
        if (lane >= d) v += n;
    }
    if (lane == 31) wsum[wid] = v;
    __syncthreads();
    if (wid == 0) {                               // all 32 lanes reach shuffles
        int w = (lane < 16) ? wsum[lane] : 0;
        #pragma unroll
        for (int d = 1; d < 16; d <<= 1) {
            int n = __shfl_up_sync(~0u, w, d);
            if (lane >= d) w += n;
        }
        if (lane < 16) wsum[lane] = w;
    }
    __syncthreads();
    int incl = v + (wid > 0 ? wsum[wid - 1] : 0);
    if (t < SCAN_NBLK) g_blockoff[t] = incl - own;   // exclusive
    if (t == 0) g_off[N_NODES] = N_EDGES;
}

__global__ void k_scan3() {                       // local scan + block offset
    __shared__ int wsum[SCAN_B / 32];
    int i = blockIdx.x * SCAN_B + threadIdx.x;
    int t = threadIdx.x, lane = t & 31, wid = t >> 5;
    int own = (i < N_NODES) ? g_cnt[i] : 0;
    int v = own;
    #pragma unroll
    for (int d = 1; d < 32; d <<= 1) {
        int n = __shfl_up_sync(~0u, v, d);
        if (lane >= d) v += n;
    }
    if (lane == 31) wsum[wid] = v;
    __syncthreads();
    if (wid == 0) {                               // FIX: full warp in shuffles
        int w = (lane < SCAN_B / 32) ? wsum[lane] : 0;
        #pragma unroll
        for (int d = 1; d < SCAN_B / 32; d <<= 1) {
            int n = __shfl_up_sync(~0u, w, d);
            if (lane >= d) w += n;
        }
        if (lane < SCAN_B / 32) wsum[lane] = w;
    }
    __syncthreads();
    if (i < N_NODES) {
        int incl = v + (wid > 0 ? wsum[wid - 1] : 0);
        int excl = incl - own + g_blockoff[blockIdx.x];
        g_off[i] = excl;
        g_cursor[i] = excl;
    }
}

// ---------------- kernel 6: scatter src into dst-sorted order ---------------
__global__ void k_scatter(const int* __restrict__ ei) {
    int e = blockIdx.x * blockDim.x + threadIdx.x;
    if (e >= N_EDGES) return;
    int src = ei[e];
    int dst = ei[N_EDGES + e];
    int pos = atomicAdd(&g_cursor[dst], 1);
    g_perm[pos] = src;
}

// ---------------- kernel 7: dst-major aggregation (no atomics, MLP=4) -------
__global__ void k_aggr(const float4* __restrict__ x4) {
    int g    = blockIdx.x * (blockDim.x >> 4) + (threadIdx.x >> 4);
    int lane = threadIdx.x & 15;
    if (g >= N_NODES) return;
    int beg = g_off[g];
    int end = g_off[g + 1];
    float4 acc = x4[(size_t)g * (DIM / 4) + lane];    // self loop
    int i = beg;
    for (; i + 4 <= end; i += 4) {
        int s0 = g_perm[i];
        int s1 = g_perm[i + 1];
        int s2 = g_perm[i + 2];
        int s3 = g_perm[i + 3];
        float4 v0 = x4[(size_t)s0 * (DIM / 4) + lane];
        float4 v1 = x4[(size_t)s1 * (DIM / 4) + lane];
        float4 v2 = x4[(size_t)s2 * (DIM / 4) + lane];
        float4 v3 = x4[(size_t)s3 * (DIM / 4) + lane];
        acc.x += (v0.x + v1.x) + (v2.x + v3.x);
        acc.y += (v0.y + v1.y) + (v2.y + v3.y);
        acc.z += (v0.z + v1.z) + (v2.z + v3.z);
        acc.w += (v0.w + v1.w) + (v2.w + v3.w);
    }
    for (; i < end; i++) {
        float4 v = x4[(size_t)g_perm[i] * (DIM / 4) + lane];
        acc.x += v.x; acc.y += v.y; acc.z += v.z; acc.w += v.w;
    }
    float inv = 1.0f / (float)(end - beg + 1);
    acc.x *= inv; acc.y *= inv; acc.z *= inv; acc.w *= inv;
    reinterpret_cast<float4*>(g_aggr)[(size_t)g * (DIM / 4) + lane] = acc;
}

// ---------------- kernel 8: register-tiled GEMM + BN partial sums -----------
__global__ void __launch_bounds__(256) k_gemm(const float* __restrict__ w,
                                              const float* __restrict__ b) {
    __shared__ float sA[GEMM_BM * DIM];   // sA[n_local*64 + k]
    __shared__ float sW[DIM * DIM];       // sW[k*64 + j] = w[j*64 + k]

    int tid = threadIdx.x;
    int tx = tid & 15;          // channel quad
    int ty = tid >> 4;          // node octet
    int n0 = blockIdx.x * GEMM_BM;

    for (int idx = tid; idx < DIM * DIM; idx += 256) {
        int j = idx >> 6, k = idx & 63;
        sW[k * DIM + j] = w[idx];
    }
    for (int idx = tid; idx < GEMM_BM * (DIM / 4); idx += 256) {
        int row = idx >> 4, q = idx & 15;
        int n = n0 + row;
        float4 v = (n < N_NODES)
            ? reinterpret_cast<const float4*>(g_aggr)[(size_t)n * (DIM / 4) + q]
            : make_float4(0.f, 0.f, 0.f, 0.f);
        *reinterpret_cast<float4*>(&sA[row * DIM + q * 4]) = v;
    }
    __syncthreads();

    float acc[8][4];
    #pragma unroll
    for (int i = 0; i < 8; i++)
        #pragma unroll
        for (int c = 0; c < 4; c++) acc[i][c] = 0.0f;

    #pragma unroll 4
    for (int k = 0; k < DIM; k++) {
        float4 wv = *reinterpret_cast<const float4*>(&sW[k * DIM + tx * 4]);
        float a[8];
        #pragma unroll
        for (int i = 0; i < 8; i++) a[i] = sA[(ty * 8 + i) * DIM + k];
        #pragma unroll
        for (int i = 0; i < 8; i++) {
            acc[i][0] = fmaf(a[i], wv.x, acc[i][0]);
            acc[i][1] = fmaf(a[i], wv.y, acc[i][1]);
            acc[i][2] = fmaf(a[i], wv.z, acc[i][2]);
            acc[i][3] = fmaf(a[i], wv.w, acc[i][3]);
        }
    }

    float4 bv = *reinterpret_cast<const float4*>(&b[tx * 4]);
    float psum[4] = {0, 0, 0, 0};
    float psq[4]  = {0, 0, 0, 0};

    #pragma unroll
    for (int i = 0; i < 8; i++) {
        int n = n0 + ty * 8 + i;
        if (n < N_NODES) {
            float4 o;
            o.x = acc[i][0] + bv.x;
            o.y = acc[i][1] + bv.y;
            o.z = acc[i][2] + bv.z;
            o.w = acc[i][3] + bv.w;
            reinterpret_cast<float4*>(g_out)[(size_t)n * (DIM / 4) + tx] = o;
            psum[0] += o.x; psum[1] += o.y; psum[2] += o.z; psum[3] += o.w;
            psq[0] += o.x * o.x; psq[1] += o.y * o.y;
            psq[2] += o.z * o.z; psq[3] += o.w * o.w;
        }
    }

    __syncthreads();
    float (*sRed)[DIM] = reinterpret_cast<float (*)[DIM]>(sA);

    #pragma unroll
    for (int c = 0; c < 4; c++) sRed[ty][tx * 4 + c] = psum[c];
    __syncthreads();
    #pragma unroll
    for (int st = 8; st > 0; st >>= 1) {
        if (ty < st)
            #pragma unroll
            for (int c = 0; c < 4; c++)
                sRed[ty][tx * 4 + c] += sRed[ty + st][tx * 4 + c];
        __syncthreads();
    }
    if (ty == 0)
        #pragma unroll
        for (int c = 0; c < 4; c++)
            atomicAdd(&g_bnsum[tx * 4 + c], sRed[0][tx * 4 + c]);
    __syncthreads();

    #pragma unroll
    for (int c = 0; c < 4; c++) sRed[ty][tx * 4 + c] = psq[c];
    __syncthreads();
    #pragma unroll
    for (int st = 8; st > 0; st >>= 1) {
        if (ty < st)
            #pragma unroll
            for (int c = 0; c < 4; c++)
                sRed[ty][tx * 4 + c] += sRed[ty + st][tx * 4 + c];
        __syncthreads();
    }
    if (ty == 0)
        #pragma unroll
        for (int c = 0; c < 4; c++)
            atomicAdd(&g_bnsq[tx * 4 + c], sRed[0][tx * 4 + c]);
}

// ---------------- kernel 9: BN finalize (64 threads) ------------------------
__global__ void k_bnfin(const float* __restrict__ gamma,
                        const float* __restrict__ beta) {
    int j = threadIdx.x;
    float invN = 1.0f / (float)N_NODES;
    float mean = g_bnsum[j] * invN;
    float var  = g_bnsq[j] * invN - mean * mean;
    float inv  = rsqrtf(var + BN_EPS);
    float sc = gamma[j] * inv;
    g_scale[j] = sc;
    g_shift[j] = beta[j] - mean * sc;
}

// ---------------- kernel 10: scale/shift + residual + relu ------------------
__global__ void k_final(const float4* __restrict__ x4, float4* __restrict__ out4) {
    int i = blockIdx.x * blockDim.x + threadIdx.x;
    if (i >= N_NODES * (DIM / 4)) return;
    int c = (i & 15) * 4;
    float4 o  = reinterpret_cast<const float4*>(g_out)[i];
    float4 xv = x4[i];
    float4 r;
    r.x = fmaxf(fmaf(o.x, g_scale[c + 0], g_shift[c + 0]) + xv.x, 0.0f);
    r.y = fmaxf(fmaf(o.y, g_scale[c + 1], g_shift[c + 1]) + xv.y, 0.0f);
    r.z = fmaxf(fmaf(o.z, g_scale[c + 2], g_shift[c + 2]) + xv.z, 0.0f);
    r.w = fmaxf(fmaf(o.w, g_scale[c + 3], g_shift[c + 3]) + xv.w, 0.0f);
    out4[i] = r;
}

// ---------------- launch -----------------------------------------------------
extern "C" void kernel_launch(void* const* d_in, const int* in_sizes, int n_in,
                              void* d_out, int out_size) {
    const float* x     = (const float*)d_in[0];
    const int*   ei    = (const int*)d_in[1];
    const float* w     = (const float*)d_in[2];
    const float* b     = (const float*)d_in[3];
    const float* gamma = (const float*)d_in[4];
    const float* beta  = (const float*)d_in[5];
    float*       out   = (float*)d_out;

    const int vec = N_NODES * (DIM / 4);

    k_zero<<<SCAN_NBLK, SCAN_B>>>();
    k_hist<<<(N_EDGES + 255) / 256, 256>>>(ei);
    k_scan1<<<SCAN_NBLK, SCAN_B>>>();
    k_scan2<<<1, 512>>>();
    k_scan3<<<SCAN_NBLK, SCAN_B>>>();
    k_scatter<<<(N_EDGES + 255) / 256, 256>>>(ei);
    k_aggr<<<(N_NODES * 16 + 255) / 256, 256>>>((const float4*)x);
    k_gemm<<<GEMM_NBLK, 256>>>(w, b);
    k_bnfin<<<1, 64>>>(gamma, beta);
    k_final<<<(vec + 255) / 256, 256>>>((const float4*)x, (float4*)out);
}